// round 2
// baseline (speedup 1.0000x reference)
#include <cuda_runtime.h>
#include <cuda_bf16.h>

// SDFVae per-part MLP:
//   inputs (metadata order):
//     d_in[0] points   [8,42,16384,3]  f32
//     d_in[1] features [8,42*8]        f32
//     d_in[2] W0       [42,32,17]      f32
//     d_in[3] W1       [42,32,32]      f32
//     d_in[4] W2       [42,32,32]      f32
//     d_in[5] W3       [42,1,32]       f32
//   output: [8,16384,42] f32, out[b][n][p]
//
// pe = [x,y,z, sin(xyz), cos(xyz)] (9) ++ features[b,p,:] (8, constant over n)
// h = relu(x@W0^T); h = relu(h@W1^T); h = relu(h@W2^T); out = h@W3^T
//
// Strategy: 1 thread = 1 point. Per-(b,p) weights staged in smem (all reads
// are warp-uniform broadcasts). The 8 feature dims of layer0 are folded into
// a per-(b,p) bias vector computed once per block.

#define B_  8
#define P_  42
#define N_  16384
#define BLOCK 256

__global__ __launch_bounds__(BLOCK)
void sdfvae_mlp_kernel(const float* __restrict__ points,
                       const float* __restrict__ features,
                       const float* __restrict__ W0,
                       const float* __restrict__ W1,
                       const float* __restrict__ W2,
                       const float* __restrict__ W3,
                       float* __restrict__ out)
{
    const int b  = blockIdx.z;
    const int p  = blockIdx.y;
    const int n0 = blockIdx.x * BLOCK;
    const int tid = threadIdx.x;

    __shared__ float sW0T[9][32];   // transposed pe-part of W0: sW0T[d][k]
    __shared__ float sB0[32];       // layer0 bias from features
    __shared__ float sW1[32][32];   // sW1[k][d]
    __shared__ float sW2[32][32];
    __shared__ float sW3[32];

    const float* w0p = W0 + p * 32 * 17;
    // stage W0 pe-columns (d<9), transposed for the d-outer loop
    for (int i = tid; i < 32 * 17; i += BLOCK) {
        int k = i / 17, d = i % 17;
        float v = w0p[i];
        if (d < 9) sW0T[d][k] = v;
    }
    const float* w1p = W1 + p * 1024;
    const float* w2p = W2 + p * 1024;
    for (int i = tid; i < 1024; i += BLOCK) {
        (&sW1[0][0])[i] = w1p[i];
        (&sW2[0][0])[i] = w2p[i];
    }
    if (tid < 32) {
        sW3[tid] = W3[p * 32 + tid];
        // fold features into layer0 bias: sB0[k] = sum_j feat[j]*W0[k][9+j]
        const float* f = features + (b * P_ + p) * 8;
        float acc = 0.f;
        #pragma unroll
        for (int j = 0; j < 8; j++)
            acc = fmaf(f[j], w0p[tid * 17 + 9 + j], acc);
        sB0[tid] = acc;
    }
    __syncthreads();

    const int n = n0 + tid;
    const float* pt = points + ((long long)((b * P_ + p)) * N_ + n) * 3;
    float x = __ldg(pt + 0), y = __ldg(pt + 1), z = __ldg(pt + 2);

    float pe[9];
    pe[0] = x; pe[1] = y; pe[2] = z;
    __sincosf(x, &pe[3], &pe[6]);
    __sincosf(y, &pe[4], &pe[7]);
    __sincosf(z, &pe[5], &pe[8]);

    float h0[32], h1[32];

    // layer 0: 9 pe dims + bias
    #pragma unroll
    for (int k = 0; k < 32; k++) h0[k] = sB0[k];
    #pragma unroll
    for (int d = 0; d < 9; d++) {
        float v = pe[d];
        #pragma unroll
        for (int k = 0; k < 32; k++)
            h0[k] = fmaf(v, sW0T[d][k], h0[k]);
    }
    #pragma unroll
    for (int k = 0; k < 32; k++) h0[k] = fmaxf(h0[k], 0.f);

    // layer 1
    #pragma unroll
    for (int k = 0; k < 32; k++) {
        float acc = 0.f;
        #pragma unroll
        for (int d = 0; d < 32; d++)
            acc = fmaf(sW1[k][d], h0[d], acc);
        h1[k] = fmaxf(acc, 0.f);
    }

    // layer 2 (reuse h0)
    #pragma unroll
    for (int k = 0; k < 32; k++) {
        float acc = 0.f;
        #pragma unroll
        for (int d = 0; d < 32; d++)
            acc = fmaf(sW2[k][d], h1[d], acc);
        h0[k] = fmaxf(acc, 0.f);
    }

    // layer 3 -> scalar
    float o = 0.f;
    #pragma unroll
    for (int d = 0; d < 32; d++)
        o = fmaf(sW3[d], h0[d], o);

    out[((long long)b * N_ + n) * P_ + p] = o;
}

extern "C" void kernel_launch(void* const* d_in, const int* in_sizes, int n_in,
                              void* d_out, int out_size)
{
    const float* points   = (const float*)d_in[0];
    const float* features = (const float*)d_in[1];
    const float* W0       = (const float*)d_in[2];
    const float* W1       = (const float*)d_in[3];
    const float* W2       = (const float*)d_in[4];
    const float* W3       = (const float*)d_in[5];
    float* out = (float*)d_out;

    dim3 grid(N_ / BLOCK, P_, B_);
    sdfvae_mlp_kernel<<<grid, BLOCK>>>(points, features, W0, W1, W2, W3, out);
}